// round 14
// baseline (speedup 1.0000x reference)
#include <cuda_runtime.h>
#include <cuda_fp16.h>
#include <cstdint>

// Problem constants (fixed: B=8192, D=128)
#define NB 8192
#define ND 128
#define NTILE 64                    // 8192 / 128 tile rows
#define GRID 296                    // exactly 2 CTAs per SM = one wave
#define MARGIN 0.5f
#define STRB 272                    // padded row stride in bytes -> conflict-free ldmatrix
#define TILE_BYTES (128 * STRB)     // 34816 per 128x128 fp16 tile
#define MAIN_TILES 2072             // 296 * 7; last 8 tiles split into 16 halves

// Device scratch (no allocation allowed; zero-initialized at load)
__device__ __align__(16) __half g_af16[NB * ND];
__device__ float g_posd[NB];
__device__ int   g_lab[NB];
__device__ int   g_maxbits[NB];
__device__ int   g_done;
__device__ int   g_sync;

// ---------------------------------------------------------------------------
// helpers
// ---------------------------------------------------------------------------
__device__ __forceinline__ uint32_t smem_u32(const void* p) {
    uint32_t a;
    asm("{ .reg .u64 t; cvta.to.shared.u64 t, %1; cvt.u32.u64 %0, t; }" : "=r"(a) : "l"(p));
    return a;
}
__device__ __forceinline__ void cpasync16(uint32_t dst, const void* src) {
    asm volatile("cp.async.cg.shared.global [%0], [%1], 16;" :: "r"(dst), "l"(src));
}
__device__ __forceinline__ void mma16816(float* c, const uint32_t* a, const uint32_t* b) {
    asm volatile(
        "mma.sync.aligned.m16n8k16.row.col.f32.f16.f16.f32 "
        "{%0,%1,%2,%3}, {%4,%5,%6,%7}, {%8,%9}, {%0,%1,%2,%3};"
        : "+f"(c[0]), "+f"(c[1]), "+f"(c[2]), "+f"(c[3])
        : "r"(a[0]), "r"(a[1]), "r"(a[2]), "r"(a[3]), "r"(b[0]), "r"(b[1]));
}
__device__ __forceinline__ void ldsm4(uint32_t* r, uint32_t addr) {
    asm volatile("ldmatrix.sync.aligned.m8n8.x4.shared.b16 {%0,%1,%2,%3}, [%4];"
        : "=r"(r[0]), "=r"(r[1]), "=r"(r[2]), "=r"(r[3]) : "r"(addr));
}

// ---------------------------------------------------------------------------
// Single fused kernel: prep -> grid barrier -> symmetric max-gram -> finalize.
// ---------------------------------------------------------------------------
__global__ void __launch_bounds__(256, 2) fused_kernel(
    const float* __restrict__ anchor,
    const float* __restrict__ positive,
    const int* __restrict__ labels,
    float* __restrict__ out
) {
    extern __shared__ char dsm[];
    __shared__ int labJ[2][128];
    __shared__ int s_last;
    __shared__ float red[256];

    const int tid  = threadIdx.x;
    const int lane = tid & 31;
    const int wid  = tid >> 5;
    const int wm   = wid & 1;         // M half (64 rows)
    const int wn   = wid >> 1;        // N quarter (32 cols)
    const int g    = lane >> 2;
    const int q    = lane & 3;
    const int bid  = blockIdx.x;

    // =====================================================================
    // Phase 1: prep (4 rows per warp; 2048 of 2368 global warps active)
    // =====================================================================
    {
        int gw = bid * 8 + wid;
        if (gw < NB / 4) {
            int r0 = gw * 4;
            float4 av[4], pv[4];
            #pragma unroll
            for (int k = 0; k < 4; k++) {
                av[k] = reinterpret_cast<const float4*>(anchor   + (size_t)(r0 + k) * ND)[lane];
                pv[k] = reinterpret_cast<const float4*>(positive + (size_t)(r0 + k) * ND)[lane];
            }
            float sa[4], sp[4];
            #pragma unroll
            for (int k = 0; k < 4; k++) {
                sa[k] = av[k].x*av[k].x + av[k].y*av[k].y + av[k].z*av[k].z + av[k].w*av[k].w;
                sp[k] = pv[k].x*pv[k].x + pv[k].y*pv[k].y + pv[k].z*pv[k].z + pv[k].w*pv[k].w;
            }
            #pragma unroll
            for (int o = 16; o > 0; o >>= 1)
                #pragma unroll
                for (int k = 0; k < 4; k++) {
                    sa[k] += __shfl_xor_sync(0xffffffffu, sa[k], o);
                    sp[k] += __shfl_xor_sync(0xffffffffu, sp[k], o);
                }
            float d2[4];
            #pragma unroll
            for (int k = 0; k < 4; k++) {
                float ia = 1.0f / fmaxf(sqrtf(sa[k]), 1e-12f);
                float ip = 1.0f / fmaxf(sqrtf(sp[k]), 1e-12f);
                float an[4] = {av[k].x*ia, av[k].y*ia, av[k].z*ia, av[k].w*ia};
                float pn[4] = {pv[k].x*ip, pv[k].y*ip, pv[k].z*ip, pv[k].w*ip};
                __half2 ha; ha.x = __float2half_rn(an[0]); ha.y = __float2half_rn(an[1]);
                __half2 hb; hb.x = __float2half_rn(an[2]); hb.y = __float2half_rn(an[3]);
                size_t base = (size_t)(r0 + k) * ND + lane * 4;
                reinterpret_cast<__half2*>(g_af16 + base)[0] = ha;
                reinterpret_cast<__half2*>(g_af16 + base)[1] = hb;
                float s = 0.0f;
                #pragma unroll
                for (int e = 0; e < 4; e++) {
                    float d = an[e] - pn[e];
                    s = fmaf(d, d, s);
                }
                d2[k] = s;
            }
            #pragma unroll
            for (int o = 16; o > 0; o >>= 1)
                #pragma unroll
                for (int k = 0; k < 4; k++)
                    d2[k] += __shfl_xor_sync(0xffffffffu, d2[k], o);
            if (lane < 4) {
                g_posd[r0 + lane]    = d2[lane];
                g_lab[r0 + lane]     = labels[r0 + lane];
                g_maxbits[r0 + lane] = 0;
            }
        }
    }

    // =====================================================================
    // Grid barrier (all 296 CTAs resident in one wave -> no deadlock)
    // =====================================================================
    __threadfence();
    __syncthreads();
    if (tid == 0) {
        atomicAdd(&g_sync, 1);
        while (*(volatile int*)&g_sync < GRID) { }
    }
    __syncthreads();

    // =====================================================================
    // Phase 2: symmetric max-gram (fp16 mma.sync, fp32 accumulate)
    // =====================================================================
    const uint32_t smb = smem_u32(dsm);
    const uint32_t aoff = (uint32_t)(wm * 64 + (lane & 15)) * STRB + (uint32_t)(lane >> 4) * 16;
    const uint32_t boff = (uint32_t)(wn * 32 + ((lane >> 4) << 3) + (lane & 7)) * STRB
                        + (uint32_t)((lane >> 3) & 1) * 16;

    const int L   = bid * 7;
    const int MYT = 7;

    int ti = 0, tbase = 0;
    while (tbase + (NTILE - ti) <= L) { tbase += NTILE - ti; ti++; }
    int tj = ti + (L - tbase);

    auto loadA = [&](int t) {
        const int i0 = t * 128;
        for (int idx = tid; idx < 2048; idx += 256) {
            int r = idx >> 4, c = idx & 15;
            cpasync16(smb + r * STRB + c * 16,
                      g_af16 + (size_t)(i0 + r) * ND + c * 8);
        }
    };
    auto loadB = [&](int t, int buf) {
        const int j0 = t * 128;
        uint32_t bb = smb + (1 + buf) * TILE_BYTES;
        for (int idx = tid; idx < 2048; idx += 256) {
            int r = idx >> 4, c = idx & 15;
            cpasync16(bb + r * STRB + c * 16,
                      g_af16 + (size_t)(j0 + r) * ND + c * 8);
        }
        if (tid < 128) labJ[buf][tid] = g_lab[j0 + tid];
    };

    int lr[4][2];
    auto loadLr = [&](int t) {
        #pragma unroll
        for (int mt = 0; mt < 4; mt++) {
            int r = t * 128 + wm * 64 + mt * 16 + g;
            lr[mt][0] = g_lab[r];
            lr[mt][1] = g_lab[r + 8];
        }
    };

    float mx[4][2];
    #pragma unroll
    for (int mt = 0; mt < 4; mt++) { mx[mt][0] = -3.0f; mx[mt][1] = -3.0f; }

    auto flushRows = [&](int t) {
        #pragma unroll
        for (int mt = 0; mt < 4; mt++)
            #pragma unroll
            for (int r = 0; r < 2; r++) {
                float v = mx[mt][r];
                v = fmaxf(v, __shfl_xor_sync(0xffffffffu, v, 1));
                v = fmaxf(v, __shfl_xor_sync(0xffffffffu, v, 2));
                if (q == 0)
                    atomicMax(&g_maxbits[t * 128 + wm * 64 + mt * 16 + g + r * 8],
                              __float_as_int(fmaxf(v + 2.0f, 0.0f)));
                mx[mt][r] = -3.0f;
            }
    };

    // prologue
    loadA(ti);
    loadB(tj, 0);
    asm volatile("cp.async.commit_group;");
    loadLr(ti);

    for (int n = 0; n < MYT; n++) {
        const int buf = n & 1;

        int ti_n = ti, tj_n = tj + 1;
        if (tj_n == NTILE) { ti_n = ti + 1; tj_n = ti_n; }

        asm volatile("cp.async.wait_group 0;" ::: "memory");
        __syncthreads();

        if (n + 1 < MYT) {
            loadB(tj_n, buf ^ 1);
            asm volatile("cp.async.commit_group;");
        }

        // ---- compute tile (ti, tj) ----
        const uint32_t Abase = smb + aoff;
        const uint32_t Bbase = smb + (1 + buf) * TILE_BYTES + boff;

        float acc[4][4][4];
        #pragma unroll
        for (int mt = 0; mt < 4; mt++)
            #pragma unroll
            for (int nt = 0; nt < 4; nt++)
                #pragma unroll
                for (int e = 0; e < 4; e++) acc[mt][nt][e] = 0.0f;

        #pragma unroll
        for (int ks = 0; ks < 8; ks++) {
            const uint32_t ko = ks * 32;
            uint32_t a[4][4], b[4][2];
            #pragma unroll
            for (int mt = 0; mt < 4; mt++)
                ldsm4(a[mt], Abase + mt * (16 * STRB) + ko);
            #pragma unroll
            for (int p = 0; p < 2; p++) {
                uint32_t rb[4];
                ldsm4(rb, Bbase + p * (16 * STRB) + ko);
                b[2*p][0] = rb[0]; b[2*p][1] = rb[1];
                b[2*p+1][0] = rb[2]; b[2*p+1][1] = rb[3];
            }
            #pragma unroll
            for (int mt = 0; mt < 4; mt++)
                #pragma unroll
                for (int nt = 0; nt < 4; nt++)
                    mma16816(acc[mt][nt], a[mt], b[nt]);
        }

        // A-prefetch for the next i-block BEFORE the epilogue (overlaps it)
        const bool tiChange = (n + 1 < MYT) && (ti_n != ti);
        if (tiChange) {
            __syncthreads();              // all warps done reading A smem
            loadA(ti_n);
            asm volatile("cp.async.commit_group;");
        }

        // ---- epilogue: mask, row-max, column-max ----
        float cmax[4][2];
        #pragma unroll
        for (int nt = 0; nt < 4; nt++) { cmax[nt][0] = -3.0f; cmax[nt][1] = -3.0f; }

        #pragma unroll
        for (int nt = 0; nt < 4; nt++) {
            int c0 = wn * 32 + nt * 8 + q * 2;
            int l0 = labJ[buf][c0], l1 = labJ[buf][c0 + 1];
            #pragma unroll
            for (int mt = 0; mt < 4; mt++) {
                float v0 = (l0 == lr[mt][0]) ? -3.0f : acc[mt][nt][0];
                float v1 = (l1 == lr[mt][0]) ? -3.0f : acc[mt][nt][1];
                float v2 = (l0 == lr[mt][1]) ? -3.0f : acc[mt][nt][2];
                float v3 = (l1 == lr[mt][1]) ? -3.0f : acc[mt][nt][3];
                mx[mt][0] = fmaxf(mx[mt][0], fmaxf(v0, v1));
                mx[mt][1] = fmaxf(mx[mt][1], fmaxf(v2, v3));
                cmax[nt][0] = fmaxf(cmax[nt][0], fmaxf(v0, v2));
                cmax[nt][1] = fmaxf(cmax[nt][1], fmaxf(v1, v3));
            }
        }

        if (ti != tj) {
            #pragma unroll
            for (int nt = 0; nt < 4; nt++)
                #pragma unroll
                for (int e = 0; e < 2; e++) {
                    float v = cmax[nt][e];
                    v = fmaxf(v, __shfl_xor_sync(0xffffffffu, v, 4));
                    v = fmaxf(v, __shfl_xor_sync(0xffffffffu, v, 8));
                    v = fmaxf(v, __shfl_xor_sync(0xffffffffu, v, 16));
                    if (g == 0)
                        atomicMax(&g_maxbits[tj * 128 + wn * 32 + nt * 8 + q * 2 + e],
                                  __float_as_int(fmaxf(v + 2.0f, 0.0f)));
                }
        }

        if (tiChange) {
            flushRows(ti);
            loadLr(ti_n);
        }
        if (n + 1 < MYT) { ti = ti_n; tj = tj_n; }
    }
    flushRows(ti);

    // =====================================================================
    // Phase 2b: remainder half-tiles. Tiles 2072..2079 split into 16
    // column-halves handled by bids 0..15 (16 distinct SMs).
    // =====================================================================
    if (bid < 16) {
        const int Lx = MAIN_TILES + (bid >> 1);
        const int half = bid & 1;
        int tix = 0, xb = 0;
        while (xb + (NTILE - tix) <= Lx) { xb += NTILE - tix; tix++; }
        int tjx = tix + (Lx - xb);
        const int j0 = tjx * 128 + half * 64;

        __syncthreads();                  // smem reuse safe
        loadA(tix);
        for (int idx = tid; idx < 1024; idx += 256) {
            int r = idx >> 4, c = idx & 15;
            cpasync16(smb + TILE_BYTES + r * STRB + c * 16,
                      g_af16 + (size_t)(j0 + r) * ND + c * 8);
        }
        if (tid < 64) labJ[0][tid] = g_lab[j0 + tid];
        asm volatile("cp.async.commit_group;");
        asm volatile("cp.async.wait_group 0;" ::: "memory");
        __syncthreads();
        loadLr(tix);

        if (wn < 2) {   // only 4 warps compute the 64 loaded cols
            const uint32_t Abase = smb + aoff;
            const uint32_t Bbase = smb + TILE_BYTES + boff;

            float acc[4][4][4];
            #pragma unroll
            for (int mt = 0; mt < 4; mt++)
                #pragma unroll
                for (int nt = 0; nt < 4; nt++)
                    #pragma unroll
                    for (int e = 0; e < 4; e++) acc[mt][nt][e] = 0.0f;

            #pragma unroll
            for (int ks = 0; ks < 8; ks++) {
                const uint32_t ko = ks * 32;
                uint32_t a[4][4], b[4][2];
                #pragma unroll
                for (int mt = 0; mt < 4; mt++)
                    ldsm4(a[mt], Abase + mt * (16 * STRB) + ko);
                #pragma unroll
                for (int p = 0; p < 2; p++) {
                    uint32_t rb[4];
                    ldsm4(rb, Bbase + p * (16 * STRB) + ko);
                    b[2*p][0] = rb[0]; b[2*p][1] = rb[1];
                    b[2*p+1][0] = rb[2]; b[2*p+1][1] = rb[3];
                }
                #pragma unroll
                for (int mt = 0; mt < 4; mt++)
                    #pragma unroll
                    for (int nt = 0; nt < 4; nt++)
                        mma16816(acc[mt][nt], a[mt], b[nt]);
            }

            float cmax[4][2];
            #pragma unroll
            for (int nt = 0; nt < 4; nt++) { cmax[nt][0] = -3.0f; cmax[nt][1] = -3.0f; }

            #pragma unroll
            for (int nt = 0; nt < 4; nt++) {
                int c0 = wn * 32 + nt * 8 + q * 2;
                int l0 = labJ[0][c0], l1 = labJ[0][c0 + 1];
                #pragma unroll
                for (int mt = 0; mt < 4; mt++) {
                    float v0 = (l0 == lr[mt][0]) ? -3.0f : acc[mt][nt][0];
                    float v1 = (l1 == lr[mt][0]) ? -3.0f : acc[mt][nt][1];
                    float v2 = (l0 == lr[mt][1]) ? -3.0f : acc[mt][nt][2];
                    float v3 = (l1 == lr[mt][1]) ? -3.0f : acc[mt][nt][3];
                    mx[mt][0] = fmaxf(mx[mt][0], fmaxf(v0, v1));
                    mx[mt][1] = fmaxf(mx[mt][1], fmaxf(v2, v3));
                    cmax[nt][0] = fmaxf(cmax[nt][0], fmaxf(v0, v2));
                    cmax[nt][1] = fmaxf(cmax[nt][1], fmaxf(v1, v3));
                }
            }

            if (tix != tjx) {   // full-128-row halves: diagonal tiles need no col-max
                #pragma unroll
                for (int nt = 0; nt < 4; nt++)
                    #pragma unroll
                    for (int e = 0; e < 2; e++) {
                        float v = cmax[nt][e];
                        v = fmaxf(v, __shfl_xor_sync(0xffffffffu, v, 4));
                        v = fmaxf(v, __shfl_xor_sync(0xffffffffu, v, 8));
                        v = fmaxf(v, __shfl_xor_sync(0xffffffffu, v, 16));
                        if (g == 0)
                            atomicMax(&g_maxbits[j0 + wn * 32 + nt * 8 + q * 2 + e],
                                      __float_as_int(fmaxf(v + 2.0f, 0.0f)));
                    }
            }
        }
        flushRows(tix);   // wn>=2 warps contribute 0-bit no-ops
    }

    // =====================================================================
    // Phase 3: fused finalize (last CTA) + counter reset for graph replay
    // =====================================================================
    __threadfence();
    if (tid == 0) s_last = (atomicAdd(&g_done, 1) == GRID - 1) ? 1 : 0;
    __syncthreads();
    if (s_last) {
        float s = 0.0f;
        for (int i = tid; i < NB; i += 256) {
            float gmax = __int_as_float(__ldcg(&g_maxbits[i])) - 2.0f;
            float neg  = fmaxf(2.0f - 2.0f * gmax, 0.0f);
            float l    = __ldcg(&g_posd[i]) - neg + MARGIN;
            s += fmaxf(l, 0.0f);
        }
        red[tid] = s;
        __syncthreads();
        #pragma unroll
        for (int stride = 128; stride > 0; stride >>= 1) {
            if (tid < stride) red[tid] += red[tid + stride];
            __syncthreads();
        }
        if (tid == 0) {
            out[0] = red[0] / (float)NB;
            g_done = 0;   // reset for next graph replay
            g_sync = 0;
        }
    }
}

extern "C" void kernel_launch(void* const* d_in, const int* in_sizes, int n_in,
                              void* d_out, int out_size) {
    const float* anchor   = (const float*)d_in[0];
    const float* positive = (const float*)d_in[1];
    const int*   labels   = (const int*)d_in[2];   // JAX x64 disabled: int64 -> int32
    float*       out      = (float*)d_out;

    const int smem = 3 * TILE_BYTES;   // 104448 B -> 2 CTAs/SM
    cudaFuncSetAttribute(fused_kernel, cudaFuncAttributeMaxDynamicSharedMemorySize, smem);
    fused_kernel<<<GRID, 256, smem>>>(anchor, positive, labels, out);
}

// round 15
// speedup vs baseline: 1.0031x; 1.0031x over previous
#include <cuda_runtime.h>
#include <cuda_fp16.h>
#include <cstdint>

// Problem constants (fixed: B=8192, D=128)
#define NB 8192
#define ND 128
#define NTILE 64                    // 8192 / 128 tile rows
#define GRID 296                    // exactly 2 CTAs per SM = one wave
#define MARGIN 0.5f
#define STRB 272                    // padded row stride in bytes -> conflict-free ldmatrix
#define TILE_BYTES (128 * STRB)     // 34816 per 128x128 fp16 tile
#define MAIN_TILES 2072             // 296 * 7; last 8 tiles split into 16 halves
#define NEG3X2 0xC200C200u          // half2(-3, -3)

// Device scratch (no allocation allowed; zero-initialized at load)
__device__ __align__(16) __half g_af16[NB * ND];
__device__ float g_posd[NB];
__device__ int   g_lab[NB];
__device__ int   g_maxbits[NB];
__device__ int   g_done;
__device__ int   g_sync;

// ---------------------------------------------------------------------------
// helpers
// ---------------------------------------------------------------------------
__device__ __forceinline__ uint32_t smem_u32(const void* p) {
    uint32_t a;
    asm("{ .reg .u64 t; cvta.to.shared.u64 t, %1; cvt.u32.u64 %0, t; }" : "=r"(a) : "l"(p));
    return a;
}
__device__ __forceinline__ void cpasync16(uint32_t dst, const void* src) {
    asm volatile("cp.async.cg.shared.global [%0], [%1], 16;" :: "r"(dst), "l"(src));
}
// fp16 inputs, fp16 accumulators (round-13 probe: same rate as f32-acc, rel_err 5.9e-6)
__device__ __forceinline__ void mma16816_f16(uint32_t* c, const uint32_t* a, const uint32_t* b) {
    asm volatile(
        "mma.sync.aligned.m16n8k16.row.col.f16.f16.f16.f16 "
        "{%0,%1}, {%2,%3,%4,%5}, {%6,%7}, {%0,%1};"
        : "+r"(c[0]), "+r"(c[1])
        : "r"(a[0]), "r"(a[1]), "r"(a[2]), "r"(a[3]), "r"(b[0]), "r"(b[1]));
}
__device__ __forceinline__ void ldsm4(uint32_t* r, uint32_t addr) {
    asm volatile("ldmatrix.sync.aligned.m8n8.x4.shared.b16 {%0,%1,%2,%3}, [%4];"
        : "=r"(r[0]), "=r"(r[1]), "=r"(r[2]), "=r"(r[3]) : "r"(addr));
}
// packed half2 ops
__device__ __forceinline__ uint32_t hmax2u(uint32_t a, uint32_t b) {
    uint32_t r;
    asm("max.f16x2 %0, %1, %2;" : "=r"(r) : "r"(a), "r"(b));
    return r;
}
__device__ __forceinline__ uint32_t heq2u(uint32_t a, uint32_t b) {   // 1.0 per equal half
    uint32_t r;
    asm("set.eq.f16x2.f16x2 %0, %1, %2;" : "=r"(r) : "r"(a), "r"(b));
    return r;
}
__device__ __forceinline__ uint32_t hsub2u(uint32_t a, uint32_t b) {
    uint32_t r;
    asm("sub.f16x2 %0, %1, %2;" : "=r"(r) : "r"(a), "r"(b));
    return r;
}
__device__ __forceinline__ uint32_t hfma2u(uint32_t a, uint32_t b, uint32_t c) {
    uint32_t r;
    asm("fma.rn.f16x2 %0, %1, %2, %3;" : "=r"(r) : "r"(a), "r"(b), "r"(c));
    return r;
}
// mask-select: v where label!=row-label, -3 where equal (m in {0,1} per half)
__device__ __forceinline__ uint32_t masksel(uint32_t lj, uint32_t lr, uint32_t v) {
    uint32_t m = heq2u(lj, lr);
    return hfma2u(m, hsub2u(NEG3X2, v), v);   // v + m*(-3 - v)
}
__device__ __forceinline__ uint32_t h2splat_int(int l) {
    __half h = __int2half_rn(l);
    uint32_t b = (uint32_t)__half_as_ushort(h);
    return b * 0x00010001u;
}

// ---------------------------------------------------------------------------
// Single fused kernel: prep -> grid barrier -> symmetric max-gram -> finalize.
// f16 MMA accumulators + fully packed half2 epilogue.
// ---------------------------------------------------------------------------
__global__ void __launch_bounds__(256, 2) fused_kernel(
    const float* __restrict__ anchor,
    const float* __restrict__ positive,
    const int* __restrict__ labels,
    float* __restrict__ out
) {
    extern __shared__ char dsm[];
    __shared__ uint32_t labJh[2][64];   // packed half2 labels (2 cols per entry)
    __shared__ int s_last;
    __shared__ float red[256];

    const int tid  = threadIdx.x;
    const int lane = tid & 31;
    const int wid  = tid >> 5;
    const int wm   = wid & 1;         // M half (64 rows)
    const int wn   = wid >> 1;        // N quarter (32 cols)
    const int g    = lane >> 2;
    const int q    = lane & 3;
    const int bid  = blockIdx.x;

    // =====================================================================
    // Phase 1: prep (4 rows per warp)
    // =====================================================================
    {
        int gw = bid * 8 + wid;
        if (gw < NB / 4) {
            int r0 = gw * 4;
            float4 av[4], pv[4];
            #pragma unroll
            for (int k = 0; k < 4; k++) {
                av[k] = reinterpret_cast<const float4*>(anchor   + (size_t)(r0 + k) * ND)[lane];
                pv[k] = reinterpret_cast<const float4*>(positive + (size_t)(r0 + k) * ND)[lane];
            }
            float sa[4], sp[4];
            #pragma unroll
            for (int k = 0; k < 4; k++) {
                sa[k] = av[k].x*av[k].x + av[k].y*av[k].y + av[k].z*av[k].z + av[k].w*av[k].w;
                sp[k] = pv[k].x*pv[k].x + pv[k].y*pv[k].y + pv[k].z*pv[k].z + pv[k].w*pv[k].w;
            }
            #pragma unroll
            for (int o = 16; o > 0; o >>= 1)
                #pragma unroll
                for (int k = 0; k < 4; k++) {
                    sa[k] += __shfl_xor_sync(0xffffffffu, sa[k], o);
                    sp[k] += __shfl_xor_sync(0xffffffffu, sp[k], o);
                }
            float d2[4];
            #pragma unroll
            for (int k = 0; k < 4; k++) {
                float ia = 1.0f / fmaxf(sqrtf(sa[k]), 1e-12f);
                float ip = 1.0f / fmaxf(sqrtf(sp[k]), 1e-12f);
                float an[4] = {av[k].x*ia, av[k].y*ia, av[k].z*ia, av[k].w*ia};
                float pn[4] = {pv[k].x*ip, pv[k].y*ip, pv[k].z*ip, pv[k].w*ip};
                __half2 ha; ha.x = __float2half_rn(an[0]); ha.y = __float2half_rn(an[1]);
                __half2 hb; hb.x = __float2half_rn(an[2]); hb.y = __float2half_rn(an[3]);
                size_t base = (size_t)(r0 + k) * ND + lane * 4;
                reinterpret_cast<__half2*>(g_af16 + base)[0] = ha;
                reinterpret_cast<__half2*>(g_af16 + base)[1] = hb;
                float s = 0.0f;
                #pragma unroll
                for (int e = 0; e < 4; e++) {
                    float d = an[e] - pn[e];
                    s = fmaf(d, d, s);
                }
                d2[k] = s;
            }
            #pragma unroll
            for (int o = 16; o > 0; o >>= 1)
                #pragma unroll
                for (int k = 0; k < 4; k++)
                    d2[k] += __shfl_xor_sync(0xffffffffu, d2[k], o);
            if (lane < 4) {
                g_posd[r0 + lane]    = d2[lane];
                g_lab[r0 + lane]     = labels[r0 + lane];
                g_maxbits[r0 + lane] = 0;
            }
        }
    }

    // =====================================================================
    // Grid barrier (all 296 CTAs resident -> no deadlock)
    // =====================================================================
    __threadfence();
    __syncthreads();
    if (tid == 0) {
        atomicAdd(&g_sync, 1);
        while (*(volatile int*)&g_sync < GRID) { }
    }
    __syncthreads();

    // =====================================================================
    // Phase 2: symmetric max-gram
    // =====================================================================
    const uint32_t smb = smem_u32(dsm);
    const uint32_t aoff = (uint32_t)(wm * 64 + (lane & 15)) * STRB + (uint32_t)(lane >> 4) * 16;
    const uint32_t boff = (uint32_t)(wn * 32 + ((lane >> 4) << 3) + (lane & 7)) * STRB
                        + (uint32_t)((lane >> 3) & 1) * 16;

    const int L   = bid * 7;
    const int MYT = 7;

    int ti = 0, tbase = 0;
    while (tbase + (NTILE - ti) <= L) { tbase += NTILE - ti; ti++; }
    int tj = ti + (L - tbase);

    auto loadA = [&](int t) {
        const int i0 = t * 128;
        for (int idx = tid; idx < 2048; idx += 256) {
            int r = idx >> 4, c = idx & 15;
            cpasync16(smb + r * STRB + c * 16,
                      g_af16 + (size_t)(i0 + r) * ND + c * 8);
        }
    };
    auto loadB = [&](int t, int buf) {
        const int j0 = t * 128;
        uint32_t bb = smb + (1 + buf) * TILE_BYTES;
        for (int idx = tid; idx < 2048; idx += 256) {
            int r = idx >> 4, c = idx & 15;
            cpasync16(bb + r * STRB + c * 16,
                      g_af16 + (size_t)(j0 + r) * ND + c * 8);
        }
        if (tid < 64) {
            int l0 = g_lab[t * 128 + 2 * tid];
            int l1 = g_lab[t * 128 + 2 * tid + 1];
            uint32_t b0 = (uint32_t)__half_as_ushort(__int2half_rn(l0));
            uint32_t b1 = (uint32_t)__half_as_ushort(__int2half_rn(l1));
            labJh[buf][tid] = b0 | (b1 << 16);
        }
    };

    uint32_t lrh[4][2];   // splat half2 of row labels (rows g, g+8 per 16-row block)
    auto loadLr = [&](int t) {
        #pragma unroll
        for (int mt = 0; mt < 4; mt++) {
            int r = t * 128 + wm * 64 + mt * 16 + g;
            lrh[mt][0] = h2splat_int(g_lab[r]);
            lrh[mt][1] = h2splat_int(g_lab[r + 8]);
        }
    };

    uint32_t rmx[4][2];   // packed running row-max (both halves same row)
    #pragma unroll
    for (int mt = 0; mt < 4; mt++) { rmx[mt][0] = NEG3X2; rmx[mt][1] = NEG3X2; }

    auto flushRows = [&](int t) {
        #pragma unroll
        for (int mt = 0; mt < 4; mt++)
            #pragma unroll
            for (int r = 0; r < 2; r++) {
                float2 f = __half22float2(*reinterpret_cast<const __half2*>(&rmx[mt][r]));
                float v = fmaxf(f.x, f.y);
                v = fmaxf(v, __shfl_xor_sync(0xffffffffu, v, 1));
                v = fmaxf(v, __shfl_xor_sync(0xffffffffu, v, 2));
                if (q == 0)
                    atomicMax(&g_maxbits[t * 128 + wm * 64 + mt * 16 + g + r * 8],
                              __float_as_int(fmaxf(v + 2.0f, 0.0f)));
                rmx[mt][r] = NEG3X2;
            }
    };

    // prologue
    loadA(ti);
    loadB(tj, 0);
    asm volatile("cp.async.commit_group;");
    loadLr(ti);

    for (int n = 0; n < MYT; n++) {
        const int buf = n & 1;

        int ti_n = ti, tj_n = tj + 1;
        if (tj_n == NTILE) { ti_n = ti + 1; tj_n = ti_n; }

        asm volatile("cp.async.wait_group 0;" ::: "memory");
        __syncthreads();

        if (n + 1 < MYT) {
            loadB(tj_n, buf ^ 1);
            asm volatile("cp.async.commit_group;");
        }

        // ---- compute tile (ti, tj): f16 accumulators ----
        const uint32_t Abase = smb + aoff;
        const uint32_t Bbase = smb + (1 + buf) * TILE_BYTES + boff;

        uint32_t acc[4][4][2];
        #pragma unroll
        for (int mt = 0; mt < 4; mt++)
            #pragma unroll
            for (int nt = 0; nt < 4; nt++) { acc[mt][nt][0] = 0u; acc[mt][nt][1] = 0u; }

        #pragma unroll
        for (int ks = 0; ks < 8; ks++) {
            const uint32_t ko = ks * 32;
            uint32_t a[4][4], b[4][2];
            #pragma unroll
            for (int mt = 0; mt < 4; mt++)
                ldsm4(a[mt], Abase + mt * (16 * STRB) + ko);
            #pragma unroll
            for (int p = 0; p < 2; p++) {
                uint32_t rb[4];
                ldsm4(rb, Bbase + p * (16 * STRB) + ko);
                b[2*p][0] = rb[0]; b[2*p][1] = rb[1];
                b[2*p+1][0] = rb[2]; b[2*p+1][1] = rb[3];
            }
            #pragma unroll
            for (int mt = 0; mt < 4; mt++)
                #pragma unroll
                for (int nt = 0; nt < 4; nt++)
                    mma16816_f16(acc[mt][nt], a[mt], b[nt]);
        }

        // A-prefetch for next i-block BEFORE the epilogue (overlaps it)
        const bool tiChange = (n + 1 < MYT) && (ti_n != ti);
        if (tiChange) {
            __syncthreads();
            loadA(ti_n);
            asm volatile("cp.async.commit_group;");
        }

        // ---- packed epilogue: mask, row-max, column-max ----
        uint32_t cmx[4];
        #pragma unroll
        for (int nt = 0; nt < 4; nt++) cmx[nt] = NEG3X2;

        #pragma unroll
        for (int nt = 0; nt < 4; nt++) {
            uint32_t lj = labJh[buf][wn * 16 + nt * 4 + q];   // cols c0, c0+1
            #pragma unroll
            for (int mt = 0; mt < 4; mt++) {
                uint32_t v0 = masksel(lj, lrh[mt][0], acc[mt][nt][0]);  // row g
                uint32_t v1 = masksel(lj, lrh[mt][1], acc[mt][nt][1]);  // row g+8
                rmx[mt][0] = hmax2u(rmx[mt][0], v0);
                rmx[mt][1] = hmax2u(rmx[mt][1], v1);
                cmx[nt]    = hmax2u(cmx[nt], hmax2u(v0, v1));
            }
        }

        if (ti != tj) {
            #pragma unroll
            for (int nt = 0; nt < 4; nt++) {
                uint32_t v = cmx[nt];
                v = hmax2u(v, __shfl_xor_sync(0xffffffffu, v, 4));
                v = hmax2u(v, __shfl_xor_sync(0xffffffffu, v, 8));
                v = hmax2u(v, __shfl_xor_sync(0xffffffffu, v, 16));
                if (g == 0) {
                    float2 f = __half22float2(*reinterpret_cast<const __half2*>(&v));
                    int c0 = tj * 128 + wn * 32 + nt * 8 + q * 2;
                    atomicMax(&g_maxbits[c0],     __float_as_int(fmaxf(f.x + 2.0f, 0.0f)));
                    atomicMax(&g_maxbits[c0 + 1], __float_as_int(fmaxf(f.y + 2.0f, 0.0f)));
                }
            }
        }

        if (tiChange) {
            flushRows(ti);
            loadLr(ti_n);
        }
        if (n + 1 < MYT) { ti = ti_n; tj = tj_n; }
    }
    flushRows(ti);

    // =====================================================================
    // Phase 2b: remainder half-tiles (tiles 2072..2079 -> 16 column-halves)
    // =====================================================================
    if (bid < 16) {
        const int Lx = MAIN_TILES + (bid >> 1);
        const int half = bid & 1;
        int tix = 0, xb = 0;
        while (xb + (NTILE - tix) <= Lx) { xb += NTILE - tix; tix++; }
        int tjx = tix + (Lx - xb);
        const int j0 = tjx * 128 + half * 64;

        __syncthreads();
        loadA(tix);
        for (int idx = tid; idx < 1024; idx += 256) {
            int r = idx >> 4, c = idx & 15;
            cpasync16(smb + TILE_BYTES + r * STRB + c * 16,
                      g_af16 + (size_t)(j0 + r) * ND + c * 8);
        }
        if (tid < 32) {
            int l0 = g_lab[j0 + 2 * tid];
            int l1 = g_lab[j0 + 2 * tid + 1];
            uint32_t b0 = (uint32_t)__half_as_ushort(__int2half_rn(l0));
            uint32_t b1 = (uint32_t)__half_as_ushort(__int2half_rn(l1));
            labJh[0][tid] = b0 | (b1 << 16);
        }
        asm volatile("cp.async.commit_group;");
        asm volatile("cp.async.wait_group 0;" ::: "memory");
        __syncthreads();
        loadLr(tix);

        if (wn < 2) {   // 4 warps compute the 64 loaded cols
            const uint32_t Abase = smb + aoff;
            const uint32_t Bbase = smb + TILE_BYTES + boff;

            uint32_t acc[4][4][2];
            #pragma unroll
            for (int mt = 0; mt < 4; mt++)
                #pragma unroll
                for (int nt = 0; nt < 4; nt++) { acc[mt][nt][0] = 0u; acc[mt][nt][1] = 0u; }

            #pragma unroll
            for (int ks = 0; ks < 8; ks++) {
                const uint32_t ko = ks * 32;
                uint32_t a[4][4], b[4][2];
                #pragma unroll
                for (int mt = 0; mt < 4; mt++)
                    ldsm4(a[mt], Abase + mt * (16 * STRB) + ko);
                #pragma unroll
                for (int p = 0; p < 2; p++) {
                    uint32_t rb[4];
                    ldsm4(rb, Bbase + p * (16 * STRB) + ko);
                    b[2*p][0] = rb[0]; b[2*p][1] = rb[1];
                    b[2*p+1][0] = rb[2]; b[2*p+1][1] = rb[3];
                }
                #pragma unroll
                for (int mt = 0; mt < 4; mt++)
                    #pragma unroll
                    for (int nt = 0; nt < 4; nt++)
                        mma16816_f16(acc[mt][nt], a[mt], b[nt]);
            }

            uint32_t cmx[4];
            #pragma unroll
            for (int nt = 0; nt < 4; nt++) cmx[nt] = NEG3X2;

            #pragma unroll
            for (int nt = 0; nt < 4; nt++) {
                uint32_t lj = labJh[0][wn * 16 + nt * 4 + q];
                #pragma unroll
                for (int mt = 0; mt < 4; mt++) {
                    uint32_t v0 = masksel(lj, lrh[mt][0], acc[mt][nt][0]);
                    uint32_t v1 = masksel(lj, lrh[mt][1], acc[mt][nt][1]);
                    rmx[mt][0] = hmax2u(rmx[mt][0], v0);
                    rmx[mt][1] = hmax2u(rmx[mt][1], v1);
                    cmx[nt]    = hmax2u(cmx[nt], hmax2u(v0, v1));
                }
            }

            if (tix != tjx) {
                #pragma unroll
                for (int nt = 0; nt < 4; nt++) {
                    uint32_t v = cmx[nt];
                    v = hmax2u(v, __shfl_xor_sync(0xffffffffu, v, 4));
                    v = hmax2u(v, __shfl_xor_sync(0xffffffffu, v, 8));
                    v = hmax2u(v, __shfl_xor_sync(0xffffffffu, v, 16));
                    if (g == 0) {
                        float2 f = __half22float2(*reinterpret_cast<const __half2*>(&v));
                        int c0 = j0 + wn * 32 + nt * 8 + q * 2;
                        atomicMax(&g_maxbits[c0],     __float_as_int(fmaxf(f.x + 2.0f, 0.0f)));
                        atomicMax(&g_maxbits[c0 + 1], __float_as_int(fmaxf(f.y + 2.0f, 0.0f)));
                    }
                }
            }
        }
        flushRows(tix);   // wn>=2 warps flush NEG3 no-ops
    }

    // =====================================================================
    // Phase 3: fused finalize (last CTA) + counter reset for graph replay
    // =====================================================================
    __threadfence();
    if (tid == 0) s_last = (atomicAdd(&g_done, 1) == GRID - 1) ? 1 : 0;
    __syncthreads();
    if (s_last) {
        float s = 0.0f;
        for (int i = tid; i < NB; i += 256) {
            float gmax = __int_as_float(__ldcg(&g_maxbits[i])) - 2.0f;
            float neg  = fmaxf(2.0f - 2.0f * gmax, 0.0f);
            float l    = __ldcg(&g_posd[i]) - neg + MARGIN;
            s += fmaxf(l, 0.0f);
        }
        red[tid] = s;
        __syncthreads();
        #pragma unroll
        for (int stride = 128; stride > 0; stride >>= 1) {
            if (tid < stride) red[tid] += red[tid + stride];
            __syncthreads();
        }
        if (tid == 0) {
            out[0] = red[0] / (float)NB;
            g_done = 0;
            g_sync = 0;
        }
    }
}

extern "C" void kernel_launch(void* const* d_in, const int* in_sizes, int n_in,
                              void* d_out, int out_size) {
    const float* anchor   = (const float*)d_in[0];
    const float* positive = (const float*)d_in[1];
    const int*   labels   = (const int*)d_in[2];   // JAX x64 disabled: int64 -> int32
    float*       out      = (float*)d_out;

    const int smem = 3 * TILE_BYTES;   // 104448 B -> 2 CTAs/SM
    cudaFuncSetAttribute(fused_kernel, cudaFuncAttributeMaxDynamicSharedMemorySize, smem);
    fused_kernel<<<GRID, 256, smem>>>(anchor, positive, labels, out);
}

// round 16
// speedup vs baseline: 1.0494x; 1.0462x over previous
#include <cuda_runtime.h>
#include <cuda_fp16.h>
#include <cstdint>

// Problem constants (fixed: B=8192, D=128)
#define NB 8192
#define ND 128
#define NTILE 64                    // 8192 / 128 tile rows
#define GRID 296                    // exactly 2 CTAs per SM = one wave
#define MARGIN 0.5f
#define STRB 272                    // padded row stride in bytes -> conflict-free ldmatrix
#define TILE_BYTES (128 * STRB)     // 34816 per 128x128 fp16 tile
#define MAIN_TILES 2072             // 296 * 7; last 8 tiles split into 16 halves
#define NEG3X2 0xC200C200u          // half2(-3, -3)

// Device scratch (no allocation allowed; zero-initialized at load)
__device__ __align__(16) __half g_af16[NB * ND];
__device__ float g_posd[NB];
__device__ int   g_lab[NB];
__device__ int   g_maxbits[NB];
__device__ int   g_done;
__device__ int   g_sync;

// ---------------------------------------------------------------------------
// helpers
// ---------------------------------------------------------------------------
__device__ __forceinline__ uint32_t smem_u32(const void* p) {
    uint32_t a;
    asm("{ .reg .u64 t; cvta.to.shared.u64 t, %1; cvt.u32.u64 %0, t; }" : "=r"(a) : "l"(p));
    return a;
}
__device__ __forceinline__ void cpasync16(uint32_t dst, const void* src) {
    asm volatile("cp.async.cg.shared.global [%0], [%1], 16;" :: "r"(dst), "l"(src));
}
// fp16 inputs, fp16 accumulators (same pipe rate as f32-acc; rel_err 5.9e-6)
__device__ __forceinline__ void mma16816_f16(uint32_t* c, const uint32_t* a, const uint32_t* b) {
    asm volatile(
        "mma.sync.aligned.m16n8k16.row.col.f16.f16.f16.f16 "
        "{%0,%1}, {%2,%3,%4,%5}, {%6,%7}, {%0,%1};"
        : "+r"(c[0]), "+r"(c[1])
        : "r"(a[0]), "r"(a[1]), "r"(a[2]), "r"(a[3]), "r"(b[0]), "r"(b[1]));
}
__device__ __forceinline__ void ldsm4(uint32_t* r, uint32_t addr) {
    asm volatile("ldmatrix.sync.aligned.m8n8.x4.shared.b16 {%0,%1,%2,%3}, [%4];"
        : "=r"(r[0]), "=r"(r[1]), "=r"(r[2]), "=r"(r[3]) : "r"(addr));
}
// packed half2 ops
__device__ __forceinline__ uint32_t hmax2u(uint32_t a, uint32_t b) {
    uint32_t r;
    asm("max.f16x2 %0, %1, %2;" : "=r"(r) : "r"(a), "r"(b));
    return r;
}
__device__ __forceinline__ uint32_t heq2u(uint32_t a, uint32_t b) {   // 1.0 per equal half
    uint32_t r;
    asm("set.eq.f16x2.f16x2 %0, %1, %2;" : "=r"(r) : "r"(a), "r"(b));
    return r;
}
__device__ __forceinline__ uint32_t hsub2u(uint32_t a, uint32_t b) {
    uint32_t r;
    asm("sub.f16x2 %0, %1, %2;" : "=r"(r) : "r"(a), "r"(b));
    return r;
}
__device__ __forceinline__ uint32_t hfma2u(uint32_t a, uint32_t b, uint32_t c) {
    uint32_t r;
    asm("fma.rn.f16x2 %0, %1, %2, %3;" : "=r"(r) : "r"(a), "r"(b), "r"(c));
    return r;
}
// mask-select: v where label!=row-label, -3 where equal (m in {0,1} per half)
__device__ __forceinline__ uint32_t masksel(uint32_t lj, uint32_t lr, uint32_t v) {
    uint32_t m = heq2u(lj, lr);
    return hfma2u(m, hsub2u(NEG3X2, v), v);   // v + m*(-3 - v)
}
__device__ __forceinline__ uint32_t h2splat_int(int l) {
    __half h = __int2half_rn(l);
    uint32_t b = (uint32_t)__half_as_ushort(h);
    return b * 0x00010001u;
}

// ---------------------------------------------------------------------------
// Single fused kernel: prep -> grid barrier -> symmetric max-gram -> finalize.
// f16 accumulators + packed epilogue + PIPELINED fragment loads.
// ---------------------------------------------------------------------------
__global__ void __launch_bounds__(256, 2) fused_kernel(
    const float* __restrict__ anchor,
    const float* __restrict__ positive,
    const int* __restrict__ labels,
    float* __restrict__ out
) {
    extern __shared__ char dsm[];
    __shared__ uint32_t labJh[2][64];   // packed half2 labels (2 cols per entry)
    __shared__ int s_last;
    __shared__ float red[256];

    const int tid  = threadIdx.x;
    const int lane = tid & 31;
    const int wid  = tid >> 5;
    const int wm   = wid & 1;         // M half (64 rows)
    const int wn   = wid >> 1;        // N quarter (32 cols)
    const int g    = lane >> 2;
    const int q    = lane & 3;
    const int bid  = blockIdx.x;

    // =====================================================================
    // Phase 1: prep (4 rows per warp)
    // =====================================================================
    {
        int gw = bid * 8 + wid;
        if (gw < NB / 4) {
            int r0 = gw * 4;
            float4 av[4], pv[4];
            #pragma unroll
            for (int k = 0; k < 4; k++) {
                av[k] = reinterpret_cast<const float4*>(anchor   + (size_t)(r0 + k) * ND)[lane];
                pv[k] = reinterpret_cast<const float4*>(positive + (size_t)(r0 + k) * ND)[lane];
            }
            float sa[4], sp[4];
            #pragma unroll
            for (int k = 0; k < 4; k++) {
                sa[k] = av[k].x*av[k].x + av[k].y*av[k].y + av[k].z*av[k].z + av[k].w*av[k].w;
                sp[k] = pv[k].x*pv[k].x + pv[k].y*pv[k].y + pv[k].z*pv[k].z + pv[k].w*pv[k].w;
            }
            #pragma unroll
            for (int o = 16; o > 0; o >>= 1)
                #pragma unroll
                for (int k = 0; k < 4; k++) {
                    sa[k] += __shfl_xor_sync(0xffffffffu, sa[k], o);
                    sp[k] += __shfl_xor_sync(0xffffffffu, sp[k], o);
                }
            float d2[4];
            #pragma unroll
            for (int k = 0; k < 4; k++) {
                float ia = 1.0f / fmaxf(sqrtf(sa[k]), 1e-12f);
                float ip = 1.0f / fmaxf(sqrtf(sp[k]), 1e-12f);
                float an[4] = {av[k].x*ia, av[k].y*ia, av[k].z*ia, av[k].w*ia};
                float pn[4] = {pv[k].x*ip, pv[k].y*ip, pv[k].z*ip, pv[k].w*ip};
                __half2 ha; ha.x = __float2half_rn(an[0]); ha.y = __float2half_rn(an[1]);
                __half2 hb; hb.x = __float2half_rn(an[2]); hb.y = __float2half_rn(an[3]);
                size_t base = (size_t)(r0 + k) * ND + lane * 4;
                reinterpret_cast<__half2*>(g_af16 + base)[0] = ha;
                reinterpret_cast<__half2*>(g_af16 + base)[1] = hb;
                float s = 0.0f;
                #pragma unroll
                for (int e = 0; e < 4; e++) {
                    float d = an[e] - pn[e];
                    s = fmaf(d, d, s);
                }
                d2[k] = s;
            }
            #pragma unroll
            for (int o = 16; o > 0; o >>= 1)
                #pragma unroll
                for (int k = 0; k < 4; k++)
                    d2[k] += __shfl_xor_sync(0xffffffffu, d2[k], o);
            if (lane < 4) {
                g_posd[r0 + lane]    = d2[lane];
                g_lab[r0 + lane]     = labels[r0 + lane];
                g_maxbits[r0 + lane] = 0;
            }
        }
    }

    // =====================================================================
    // Grid barrier (all 296 CTAs resident -> no deadlock)
    // =====================================================================
    __threadfence();
    __syncthreads();
    if (tid == 0) {
        atomicAdd(&g_sync, 1);
        while (*(volatile int*)&g_sync < GRID) { }
    }
    __syncthreads();

    // =====================================================================
    // Phase 2: symmetric max-gram
    // =====================================================================
    const uint32_t smb = smem_u32(dsm);
    const uint32_t aoff = (uint32_t)(wm * 64 + (lane & 15)) * STRB + (uint32_t)(lane >> 4) * 16;
    const uint32_t boff = (uint32_t)(wn * 32 + ((lane >> 4) << 3) + (lane & 7)) * STRB
                        + (uint32_t)((lane >> 3) & 1) * 16;

    const int L   = bid * 7;
    const int MYT = 7;

    int ti = 0, tbase = 0;
    while (tbase + (NTILE - ti) <= L) { tbase += NTILE - ti; ti++; }
    int tj = ti + (L - tbase);

    auto loadA = [&](int t) {
        const int i0 = t * 128;
        for (int idx = tid; idx < 2048; idx += 256) {
            int r = idx >> 4, c = idx & 15;
            cpasync16(smb + r * STRB + c * 16,
                      g_af16 + (size_t)(i0 + r) * ND + c * 8);
        }
    };
    auto loadB = [&](int t, int buf) {
        const int j0 = t * 128;
        uint32_t bb = smb + (1 + buf) * TILE_BYTES;
        for (int idx = tid; idx < 2048; idx += 256) {
            int r = idx >> 4, c = idx & 15;
            cpasync16(bb + r * STRB + c * 16,
                      g_af16 + (size_t)(j0 + r) * ND + c * 8);
        }
        if (tid < 64) {
            int l0 = g_lab[t * 128 + 2 * tid];
            int l1 = g_lab[t * 128 + 2 * tid + 1];
            uint32_t b0 = (uint32_t)__half_as_ushort(__int2half_rn(l0));
            uint32_t b1 = (uint32_t)__half_as_ushort(__int2half_rn(l1));
            labJh[buf][tid] = b0 | (b1 << 16);
        }
    };

    uint32_t lrh[4][2];
    auto loadLr = [&](int t) {
        #pragma unroll
        for (int mt = 0; mt < 4; mt++) {
            int r = t * 128 + wm * 64 + mt * 16 + g;
            lrh[mt][0] = h2splat_int(g_lab[r]);
            lrh[mt][1] = h2splat_int(g_lab[r + 8]);
        }
    };

    uint32_t rmx[4][2];
    #pragma unroll
    for (int mt = 0; mt < 4; mt++) { rmx[mt][0] = NEG3X2; rmx[mt][1] = NEG3X2; }

    auto flushRows = [&](int t) {
        #pragma unroll
        for (int mt = 0; mt < 4; mt++)
            #pragma unroll
            for (int r = 0; r < 2; r++) {
                float2 f = __half22float2(*reinterpret_cast<const __half2*>(&rmx[mt][r]));
                float v = fmaxf(f.x, f.y);
                v = fmaxf(v, __shfl_xor_sync(0xffffffffu, v, 1));
                v = fmaxf(v, __shfl_xor_sync(0xffffffffu, v, 2));
                if (q == 0)
                    atomicMax(&g_maxbits[t * 128 + wm * 64 + mt * 16 + g + r * 8],
                              __float_as_int(fmaxf(v + 2.0f, 0.0f)));
                rmx[mt][r] = NEG3X2;
            }
    };

    // pipelined fragment loader: fills a[4][4] and b[4][2] for k-step ks
    auto loadFrags = [&](uint32_t Abase, uint32_t Bbase, int ks,
                         uint32_t a[4][4], uint32_t b[4][2]) {
        const uint32_t ko = (uint32_t)ks * 32;
        #pragma unroll
        for (int mt = 0; mt < 4; mt++)
            ldsm4(a[mt], Abase + mt * (16 * STRB) + ko);
        #pragma unroll
        for (int p = 0; p < 2; p++) {
            uint32_t rb[4];
            ldsm4(rb, Bbase + p * (16 * STRB) + ko);
            b[2*p][0] = rb[0]; b[2*p][1] = rb[1];
            b[2*p+1][0] = rb[2]; b[2*p+1][1] = rb[3];
        }
    };

    // prologue
    loadA(ti);
    loadB(tj, 0);
    asm volatile("cp.async.commit_group;");
    loadLr(ti);

    for (int n = 0; n < MYT; n++) {
        const int buf = n & 1;

        int ti_n = ti, tj_n = tj + 1;
        if (tj_n == NTILE) { ti_n = ti + 1; tj_n = ti_n; }

        asm volatile("cp.async.wait_group 0;" ::: "memory");
        __syncthreads();

        if (n + 1 < MYT) {
            loadB(tj_n, buf ^ 1);
            asm volatile("cp.async.commit_group;");
        }

        // ---- compute tile (ti, tj): pipelined frags, f16 accumulators ----
        const uint32_t Abase = smb + aoff;
        const uint32_t Bbase = smb + (1 + buf) * TILE_BYTES + boff;

        uint32_t acc[4][4][2];
        #pragma unroll
        for (int mt = 0; mt < 4; mt++)
            #pragma unroll
            for (int nt = 0; nt < 4; nt++) { acc[mt][nt][0] = 0u; acc[mt][nt][1] = 0u; }

        uint32_t afr[2][4][4], bfr[2][4][2];
        loadFrags(Abase, Bbase, 0, afr[0], bfr[0]);
        #pragma unroll
        for (int ks = 0; ks < 8; ks++) {
            const int cur = ks & 1, nxt = cur ^ 1;
            if (ks < 7)
                loadFrags(Abase, Bbase, ks + 1, afr[nxt], bfr[nxt]);
            #pragma unroll
            for (int mt = 0; mt < 4; mt++)
                #pragma unroll
                for (int nt = 0; nt < 4; nt++)
                    mma16816_f16(acc[mt][nt], afr[cur][mt], bfr[cur][nt]);
        }

        // A-prefetch for next i-block BEFORE the epilogue (overlaps it)
        const bool tiChange = (n + 1 < MYT) && (ti_n != ti);
        if (tiChange) {
            __syncthreads();
            loadA(ti_n);
            asm volatile("cp.async.commit_group;");
        }

        // ---- packed epilogue: mask, row-max, column-max ----
        uint32_t cmx[4];
        #pragma unroll
        for (int nt = 0; nt < 4; nt++) cmx[nt] = NEG3X2;

        #pragma unroll
        for (int nt = 0; nt < 4; nt++) {
            uint32_t lj = labJh[buf][wn * 16 + nt * 4 + q];
            #pragma unroll
            for (int mt = 0; mt < 4; mt++) {
                uint32_t v0 = masksel(lj, lrh[mt][0], acc[mt][nt][0]);
                uint32_t v1 = masksel(lj, lrh[mt][1], acc[mt][nt][1]);
                rmx[mt][0] = hmax2u(rmx[mt][0], v0);
                rmx[mt][1] = hmax2u(rmx[mt][1], v1);
                cmx[nt]    = hmax2u(cmx[nt], hmax2u(v0, v1));
            }
        }

        if (ti != tj) {
            #pragma unroll
            for (int nt = 0; nt < 4; nt++) {
                uint32_t v = cmx[nt];
                v = hmax2u(v, __shfl_xor_sync(0xffffffffu, v, 4));
                v = hmax2u(v, __shfl_xor_sync(0xffffffffu, v, 8));
                v = hmax2u(v, __shfl_xor_sync(0xffffffffu, v, 16));
                if (g == 0) {
                    float2 f = __half22float2(*reinterpret_cast<const __half2*>(&v));
                    int c0 = tj * 128 + wn * 32 + nt * 8 + q * 2;
                    atomicMax(&g_maxbits[c0],     __float_as_int(fmaxf(f.x + 2.0f, 0.0f)));
                    atomicMax(&g_maxbits[c0 + 1], __float_as_int(fmaxf(f.y + 2.0f, 0.0f)));
                }
            }
        }

        if (tiChange) {
            flushRows(ti);
            loadLr(ti_n);
        }
        if (n + 1 < MYT) { ti = ti_n; tj = tj_n; }
    }
    flushRows(ti);

    // =====================================================================
    // Phase 2b: remainder half-tiles (tiles 2072..2079 -> 16 column-halves)
    // =====================================================================
    if (bid < 16) {
        const int Lx = MAIN_TILES + (bid >> 1);
        const int half = bid & 1;
        int tix = 0, xb = 0;
        while (xb + (NTILE - tix) <= Lx) { xb += NTILE - tix; tix++; }
        int tjx = tix + (Lx - xb);
        const int j0 = tjx * 128 + half * 64;

        __syncthreads();
        loadA(tix);
        for (int idx = tid; idx < 1024; idx += 256) {
            int r = idx >> 4, c = idx & 15;
            cpasync16(smb + TILE_BYTES + r * STRB + c * 16,
                      g_af16 + (size_t)(j0 + r) * ND + c * 8);
        }
        if (tid < 32) {
            int l0 = g_lab[j0 + 2 * tid];
            int l1 = g_lab[j0 + 2 * tid + 1];
            uint32_t b0 = (uint32_t)__half_as_ushort(__int2half_rn(l0));
            uint32_t b1 = (uint32_t)__half_as_ushort(__int2half_rn(l1));
            labJh[0][tid] = b0 | (b1 << 16);
        }
        asm volatile("cp.async.commit_group;");
        asm volatile("cp.async.wait_group 0;" ::: "memory");
        __syncthreads();
        loadLr(tix);

        if (wn < 2) {
            const uint32_t Abase = smb + aoff;
            const uint32_t Bbase = smb + TILE_BYTES + boff;

            uint32_t acc[4][4][2];
            #pragma unroll
            for (int mt = 0; mt < 4; mt++)
                #pragma unroll
                for (int nt = 0; nt < 4; nt++) { acc[mt][nt][0] = 0u; acc[mt][nt][1] = 0u; }

            uint32_t afr[2][4][4], bfr[2][4][2];
            loadFrags(Abase, Bbase, 0, afr[0], bfr[0]);
            #pragma unroll
            for (int ks = 0; ks < 8; ks++) {
                const int cur = ks & 1, nxt = cur ^ 1;
                if (ks < 7)
                    loadFrags(Abase, Bbase, ks + 1, afr[nxt], bfr[nxt]);
                #pragma unroll
                for (int mt = 0; mt < 4; mt++)
                    #pragma unroll
                    for (int nt = 0; nt < 4; nt++)
                        mma16816_f16(acc[mt][nt], afr[cur][mt], bfr[cur][nt]);
            }

            uint32_t cmx[4];
            #pragma unroll
            for (int nt = 0; nt < 4; nt++) cmx[nt] = NEG3X2;

            #pragma unroll
            for (int nt = 0; nt < 4; nt++) {
                uint32_t lj = labJh[0][wn * 16 + nt * 4 + q];
                #pragma unroll
                for (int mt = 0; mt < 4; mt++) {
                    uint32_t v0 = masksel(lj, lrh[mt][0], acc[mt][nt][0]);
                    uint32_t v1 = masksel(lj, lrh[mt][1], acc[mt][nt][1]);
                    rmx[mt][0] = hmax2u(rmx[mt][0], v0);
                    rmx[mt][1] = hmax2u(rmx[mt][1], v1);
                    cmx[nt]    = hmax2u(cmx[nt], hmax2u(v0, v1));
                }
            }

            if (tix != tjx) {
                #pragma unroll
                for (int nt = 0; nt < 4; nt++) {
                    uint32_t v = cmx[nt];
                    v = hmax2u(v, __shfl_xor_sync(0xffffffffu, v, 4));
                    v = hmax2u(v, __shfl_xor_sync(0xffffffffu, v, 8));
                    v = hmax2u(v, __shfl_xor_sync(0xffffffffu, v, 16));
                    if (g == 0) {
                        float2 f = __half22float2(*reinterpret_cast<const __half2*>(&v));
                        int c0 = j0 + wn * 32 + nt * 8 + q * 2;
                        atomicMax(&g_maxbits[c0],     __float_as_int(fmaxf(f.x + 2.0f, 0.0f)));
                        atomicMax(&g_maxbits[c0 + 1], __float_as_int(fmaxf(f.y + 2.0f, 0.0f)));
                    }
                }
            }
        }
        flushRows(tix);
    }

    // =====================================================================
    // Phase 3: fused finalize (last CTA) + counter reset for graph replay
    // =====================================================================
    __threadfence();
    if (tid == 0) s_last = (atomicAdd(&g_done, 1) == GRID - 1) ? 1 : 0;
    __syncthreads();
    if (s_last) {
        float s = 0.0f;
        for (int i = tid; i < NB; i += 256) {
            float gmax = __int_as_float(__ldcg(&g_maxbits[i])) - 2.0f;
            float neg  = fmaxf(2.0f - 2.0f * gmax, 0.0f);
            float l    = __ldcg(&g_posd[i]) - neg + MARGIN;
            s += fmaxf(l, 0.0f);
        }
        red[tid] = s;
        __syncthreads();
        #pragma unroll
        for (int stride = 128; stride > 0; stride >>= 1) {
            if (tid < stride) red[tid] += red[tid + stride];
            __syncthreads();
        }
        if (tid == 0) {
            out[0] = red[0] / (float)NB;
            g_done = 0;
            g_sync = 0;
        }
    }
}

extern "C" void kernel_launch(void* const* d_in, const int* in_sizes, int n_in,
                              void* d_out, int out_size) {
    const float* anchor   = (const float*)d_in[0];
    const float* positive = (const float*)d_in[1];
    const int*   labels   = (const int*)d_in[2];   // JAX x64 disabled: int64 -> int32
    float*       out      = (float*)d_out;

    const int smem = 3 * TILE_BYTES;   // 104448 B -> 2 CTAs/SM
    cudaFuncSetAttribute(fused_kernel, cudaFuncAttributeMaxDynamicSharedMemorySize, smem);
    fused_kernel<<<GRID, 256, smem>>>(anchor, positive, labels, out);
}